// round 6
// baseline (speedup 1.0000x reference)
#include <cuda_runtime.h>
#include <cstdint>

// Fixed shapes per reference: B=256, L=512, N=50000
constexpr int B_SZ   = 256;
constexpr int L_SEQ  = 512;
constexpr int N_LOC  = 50000;                 // 200,000 bytes per row
constexpr int HSIZE  = 1024;                  // hash slots (pow2), load factor <= 0.5
constexpr int NT     = 256;
constexpr int SEGS   = 4;                     // CTAs per row
constexpr int SEG_ELEMS = N_LOC / SEGS;       // 12,500 elements
constexpr int SEG_BYTES = SEG_ELEMS * 4;      // 50,000 bytes (multiple of 16)
constexpr int BUF_BYTES = 12288;              // smem zero buffer (multiple of 16)

__device__ __forceinline__ uint32_t smem_u32(const void* p) {
    uint32_t a;
    asm("{ .reg .u64 t; cvta.to.shared.u64 t, %1; cvt.u32.u64 %0, t; }" : "=r"(a) : "l"(p));
    return a;
}

__global__ __launch_bounds__(NT, 8)
void fused_kernel(const int* __restrict__ loc_seq,
                  const int* __restrict__ mask,
                  const float* __restrict__ rw_p,
                  const float* __restrict__ fw_p,
                  float* __restrict__ out)
{
    const int b   = blockIdx.x / SEGS;        // batch row
    const int q   = blockIdx.x % SEGS;        // segment within row
    const int tid = threadIdx.x;

    __shared__ float4   buf[BUF_BYTES / 16];  // zero source for bulk copies
    __shared__ int      h_key[HSIZE];
    __shared__ int      h_cnt[HSIZE];
    __shared__ unsigned h_rec[HSIZE];         // float bits; all values >= 0
    __shared__ int      s_maxcnt;

    // ---- init zero buffer + hash (parallel) ----
    const float4 z = make_float4(0.f, 0.f, 0.f, 0.f);
    #pragma unroll
    for (int i = tid; i < BUF_BYTES / 16; i += NT) buf[i] = z;
    #pragma unroll 4
    for (int i = tid; i < HSIZE; i += NT) {
        h_key[i] = -1;
        h_cnt[i] = 0;
        h_rec[i] = 0u;
    }
    if (tid == 0) s_maxcnt = 0;
    __syncthreads();
    // order generic smem writes before async-proxy reads of buf
    asm volatile("fence.proxy.async.shared::cta;" ::: "memory");

    // ---- launch async bulk-zero of this CTA's own 50 KB segment ----
    if (tid == 0) {
        char* dst = (char*)out + (size_t)b * (N_LOC * 4) + (size_t)q * SEG_BYTES;
        uint32_t src = smem_u32(buf);
        int rem = SEG_BYTES;
        while (rem > 0) {
            int c = rem < BUF_BYTES ? rem : BUF_BYTES;
            asm volatile(
                "cp.async.bulk.global.shared::cta.bulk_group [%0], [%1], %2;"
                :: "l"(dst), "r"(src), "r"(c) : "memory");
            dst += c; rem -= c;
        }
        asm volatile("cp.async.bulk.commit_group;" ::: "memory");
    }

    // ---- build the full-row hash (hidden under the TMA stores) ----
    const float l2rw = log2f(*rw_p);

    const int2* lrow = reinterpret_cast<const int2*>(loc_seq + (size_t)b * L_SEQ);
    const int2* mrow = reinterpret_cast<const int2*>(mask    + (size_t)b * L_SEQ);
    const int2 lk = lrow[tid];
    const int2 mk = mrow[tid];

    #pragma unroll
    for (int j = 0; j < 2; j++) {
        const int t   = 2 * tid + j;
        const int key = (j == 0) ? lk.x : lk.y;
        const int m   = (j == 0) ? mk.x : mk.y;
        const float rec = m ? exp2f((float)(L_SEQ - 1 - t) * l2rw) : 0.0f;

        unsigned h = ((unsigned)key * 2654435761u) & (HSIZE - 1);
        for (;;) {
            int cur = h_key[h];
            if (cur == key) break;
            if (cur == -1) {
                int prev = atomicCAS(&h_key[h], -1, key);
                if (prev == -1 || prev == key) break;
            }
            h = (h + 1) & (HSIZE - 1);
        }
        atomicAdd(&h_cnt[h], m);
        atomicMax(&h_rec[h], __float_as_uint(rec));
    }
    __syncthreads();

    // ---- block reduce: max frequency count ----
    int mf = 0;
    #pragma unroll 4
    for (int i = tid; i < HSIZE; i += NT) mf = max(mf, h_cnt[i]);
    #pragma unroll
    for (int o = 16; o > 0; o >>= 1) mf = max(mf, __shfl_xor_sync(0xFFFFFFFFu, mf, o));
    if ((tid & 31) == 0) atomicMax(&s_maxcnt, mf);

    // ---- wait for own bulk-zero to complete (local dependency only) ----
    if (tid == 0)
        asm volatile("cp.async.bulk.wait_group 0;" ::: "memory");
    __syncthreads();

    const float inv = (*fw_p) / fmaxf((float)s_maxcnt, 1.0f);

    // ---- scatter hash entries falling in this CTA's segment ----
    const int col0 = q * SEG_ELEMS;
    const int col1 = col0 + SEG_ELEMS;
    float* row = out + (size_t)b * N_LOC;

    #pragma unroll 4
    for (int i = tid; i < HSIZE; i += NT) {
        const int key = h_key[i];
        if (key >= col0 && key < col1) {
            row[key] = __uint_as_float(h_rec[i]) + (float)h_cnt[i] * inv;
        }
    }
}

extern "C" void kernel_launch(void* const* d_in, const int* in_sizes, int n_in,
                              void* d_out, int out_size)
{
    const int*   loc_seq = (const int*)  d_in[0];   // (B, L) int32
    const int*   mask    = (const int*)  d_in[1];   // (B, L) int32
    const float* rw      = (const float*)d_in[2];   // scalar
    const float* fw      = (const float*)d_in[3];   // scalar
    float*       out     = (float*)d_out;           // (B, N) float32

    fused_kernel<<<B_SZ * SEGS, NT>>>(loc_seq, mask, rw, fw, out);
}

// round 7
// speedup vs baseline: 1.1336x; 1.1336x over previous
#include <cuda_runtime.h>
#include <cstdint>

// Fixed shapes per reference: B=256, L=512, N=50000
constexpr int B_SZ   = 256;
constexpr int L_SEQ  = 512;
constexpr int N_LOC  = 50000;                  // 200,000 bytes per row (16B multiple)
constexpr int HSIZE  = 1024;                   // hash slots (pow2), load factor 0.5
constexpr int NT     = 512;
constexpr int ROW_BYTES = N_LOC * 4;           // 200,000
constexpr int BUF_BYTES = 16384;               // smem zero buffer (16B multiple)

__device__ __forceinline__ uint32_t smem_u32(const void* p) {
    uint32_t a;
    asm("{ .reg .u64 t; cvta.to.shared.u64 t, %1; cvt.u32.u64 %0, t; }" : "=r"(a) : "l"(p));
    return a;
}

__global__ __launch_bounds__(NT, 4)
void fused_kernel(const int* __restrict__ loc_seq,
                  const int* __restrict__ mask,
                  const float* __restrict__ rw_p,
                  const float* __restrict__ fw_p,
                  float* __restrict__ out)
{
    const int b   = blockIdx.x;                // one CTA per batch row
    const int tid = threadIdx.x;

    __shared__ float4   buf[BUF_BYTES / 16];   // zero source for bulk copies
    __shared__ int      h_key[HSIZE];
    __shared__ int      h_cnt[HSIZE];
    __shared__ unsigned h_rec[HSIZE];          // float bits; all values >= 0
    __shared__ int      s_maxcnt;

    // ---- init zero buffer + hash (parallel across 512 threads) ----
    const float4 z = make_float4(0.f, 0.f, 0.f, 0.f);
    #pragma unroll
    for (int i = tid; i < BUF_BYTES / 16; i += NT) buf[i] = z;
    #pragma unroll
    for (int i = tid; i < HSIZE; i += NT) {
        h_key[i] = -1;
        h_cnt[i] = 0;
        h_rec[i] = 0u;
    }
    if (tid == 0) s_maxcnt = 0;
    __syncthreads();
    // order generic smem writes before async-proxy reads of buf
    asm volatile("fence.proxy.async.shared::cta;" ::: "memory");

    // ---- kick off async bulk-zero of the ENTIRE row (200 KB) ----
    if (tid == 0) {
        char* dst = (char*)out + (size_t)b * ROW_BYTES;
        uint32_t src = smem_u32(buf);
        int rem = ROW_BYTES;
        while (rem > 0) {
            int c = rem < BUF_BYTES ? rem : BUF_BYTES;
            asm volatile(
                "cp.async.bulk.global.shared::cta.bulk_group [%0], [%1], %2;"
                :: "l"(dst), "r"(src), "r"(c) : "memory");
            dst += c; rem -= c;
        }
        asm volatile("cp.async.bulk.commit_group;" ::: "memory");
    }

    // ---- build the row hash ONCE (1 timestep per thread), hidden under TMA ----
    const float l2rw = log2f(*rw_p);
    {
        const int t   = tid;
        const int key = loc_seq[(size_t)b * L_SEQ + t];
        const int m   = mask   [(size_t)b * L_SEQ + t];
        const float rec = m ? exp2f((float)(L_SEQ - 1 - t) * l2rw) : 0.0f;

        unsigned h = ((unsigned)key * 2654435761u) & (HSIZE - 1);
        for (;;) {
            int cur = h_key[h];
            if (cur == key) break;
            if (cur == -1) {
                int prev = atomicCAS(&h_key[h], -1, key);
                if (prev == -1 || prev == key) break;
            }
            h = (h + 1) & (HSIZE - 1);
        }
        atomicAdd(&h_cnt[h], m);
        atomicMax(&h_rec[h], __float_as_uint(rec));
    }
    __syncthreads();

    // ---- block reduce: max frequency count (2 slots per thread) ----
    int mf = max(h_cnt[tid], h_cnt[tid + NT]);
    #pragma unroll
    for (int o = 16; o > 0; o >>= 1) mf = max(mf, __shfl_xor_sync(0xFFFFFFFFu, mf, o));
    if ((tid & 31) == 0) atomicMax(&s_maxcnt, mf);

    // ---- wait for own bulk-zero to complete (purely local dependency) ----
    if (tid == 0)
        asm volatile("cp.async.bulk.wait_group 0;" ::: "memory");
    __syncthreads();

    const float inv = (*fw_p) / fmaxf((float)s_maxcnt, 1.0f);

    // ---- scatter final values over the zeroed row (2 slots per thread) ----
    float* row = out + (size_t)b * N_LOC;
    #pragma unroll
    for (int i = tid; i < HSIZE; i += NT) {
        const int key = h_key[i];
        if (key >= 0) {
            row[key] = __uint_as_float(h_rec[i]) + (float)h_cnt[i] * inv;
        }
    }
}

extern "C" void kernel_launch(void* const* d_in, const int* in_sizes, int n_in,
                              void* d_out, int out_size)
{
    const int*   loc_seq = (const int*)  d_in[0];   // (B, L) int32
    const int*   mask    = (const int*)  d_in[1];   // (B, L) int32
    const float* rw      = (const float*)d_in[2];   // scalar
    const float* fw      = (const float*)d_in[3];   // scalar
    float*       out     = (float*)d_out;           // (B, N) float32

    fused_kernel<<<B_SZ, NT>>>(loc_seq, mask, rw, fw, out);
}